// round 1
// baseline (speedup 1.0000x reference)
#include <cuda_runtime.h>
#include <math.h>

// Problem dims
#define Bsz  256
#define Tsz  256
#define INsz 4
#define HPsz 64
#define Esz  512
#define Hsz  1024
#define Dsz  4
#define ROWS (Bsz * Tsz)   // 65536

// Scratch (device globals; no allocation allowed)
__device__ float g_x[(size_t)ROWS * Esz];    // residual stream [B*T, E]   128 MB
__device__ float g_h1[(size_t)ROWS * Hsz];   // hidden          [B*T, H]   256 MB
__device__ float g_h2[(size_t)ROWS * Esz];   // layer out       [B*T, E]   128 MB

// ---------------------------------------------------------------------------
// Input projector: x = gelu(hist @ W1 + b1) @ W2 + b2   (exact GELU)
// one block (128 thr) per row
// ---------------------------------------------------------------------------
__global__ void proj_kernel(const float* __restrict__ hist,
                            const float* __restrict__ W1, const float* __restrict__ b1,
                            const float* __restrict__ W2, const float* __restrict__ b2,
                            float* __restrict__ out) {
    __shared__ float inr[INsz];
    __shared__ float hp[HPsz];
    int row = blockIdx.x;
    int tid = threadIdx.x;

    if (tid < INsz) inr[tid] = hist[(size_t)row * INsz + tid];
    __syncthreads();

    if (tid < HPsz) {
        float a = b1[tid];
#pragma unroll
        for (int i = 0; i < INsz; i++) a += inr[i] * W1[i * HPsz + tid];
        // exact GELU: 0.5 * x * (1 + erf(x / sqrt(2)))
        hp[tid] = 0.5f * a * (1.0f + erff(a * 0.70710678118654752440f));
    }
    __syncthreads();

    for (int o = tid; o < Esz; o += 128) {
        float a = b2[o];
#pragma unroll 8
        for (int j = 0; j < HPsz; j++) a += hp[j] * W2[j * Esz + o];
        out[(size_t)row * Esz + o] = a;
    }
}

// ---------------------------------------------------------------------------
// SGEMM with fused bias: C[M,N] = A[M,K] @ B[K,N] + bias[N]
// 128x128 tile, BK=8, 256 threads, 8x8 per-thread microtile
// M % 128 == 0, N % 128 == 0, K % 8 == 0 (all hold here)
// ---------------------------------------------------------------------------
#define BM 128
#define BN 128
#define BKQ 8
#define TM 8
#define TN 8

__global__ __launch_bounds__(256, 2)
void sgemm_bias(const float* __restrict__ A, const float* __restrict__ B,
                const float* __restrict__ bias, float* __restrict__ C,
                int M, int N, int K) {
    __shared__ float As[BKQ][BM];
    __shared__ float Bs[BKQ][BN];

    int bx = blockIdx.x;   // N tile
    int by = blockIdx.y;   // M tile
    int tid = threadIdx.x;

    int tcol = tid & 15;   // 16 thread-cols * TN = 128
    int trow = tid >> 4;   // 16 thread-rows * TM = 128

    // A tile load: 128 x 8, one float4 per thread
    int aRow = tid >> 1;
    int aCol = (tid & 1) * 4;
    // B tile load: 8 x 128, one float4 per thread
    int bRow = tid >> 5;
    int bCol = (tid & 31) * 4;

    const float* Ab = A + (size_t)(by * BM) * K;
    const float* Bb = B + bx * BN;

    float acc[TM][TN] = {};

    for (int k0 = 0; k0 < K; k0 += BKQ) {
        float4 a4 = *(const float4*)(Ab + (size_t)aRow * K + k0 + aCol);
        As[aCol + 0][aRow] = a4.x;
        As[aCol + 1][aRow] = a4.y;
        As[aCol + 2][aRow] = a4.z;
        As[aCol + 3][aRow] = a4.w;
        float4 b4 = *(const float4*)(Bb + (size_t)(k0 + bRow) * N + bCol);
        *(float4*)&Bs[bRow][bCol] = b4;
        __syncthreads();

#pragma unroll
        for (int k = 0; k < BKQ; k++) {
            float ra[TM], rb[TN];
            *(float4*)&ra[0] = *(const float4*)&As[k][trow * TM];
            *(float4*)&ra[4] = *(const float4*)&As[k][trow * TM + 4];
            *(float4*)&rb[0] = *(const float4*)&Bs[k][tcol * TN];
            *(float4*)&rb[4] = *(const float4*)&Bs[k][tcol * TN + 4];
#pragma unroll
            for (int i = 0; i < TM; i++)
#pragma unroll
                for (int j = 0; j < TN; j++)
                    acc[i][j] += ra[i] * rb[j];
        }
        __syncthreads();
    }

    float bs[TN];
#pragma unroll
    for (int j = 0; j < TN; j++) bs[j] = bias[bx * BN + tcol * TN + j];

#pragma unroll
    for (int i = 0; i < TM; i++) {
        size_t row = (size_t)(by * BM + trow * TM + i);
        float* Cp = C + row * N + bx * BN + tcol * TN;
#pragma unroll
        for (int j = 0; j < TN; j += 4) {
            float4 v;
            v.x = acc[i][j + 0] + bs[j + 0];
            v.y = acc[i][j + 1] + bs[j + 1];
            v.z = acc[i][j + 2] + bs[j + 2];
            v.w = acc[i][j + 3] + bs[j + 3];
            *(float4*)(Cp + j) = v;
        }
    }
}

// ---------------------------------------------------------------------------
// Block reduction helper
// ---------------------------------------------------------------------------
__device__ __forceinline__ float block_reduce_sum(float v) {
    __shared__ float sm[32];
    int lane = threadIdx.x & 31, wid = threadIdx.x >> 5;
#pragma unroll
    for (int o = 16; o > 0; o >>= 1) v += __shfl_xor_sync(0xffffffffu, v, o);
    __syncthreads();  // protect sm reuse across calls
    if (lane == 0) sm[wid] = v;
    __syncthreads();
    if (wid == 0) {
        v = (lane < (int)(blockDim.x >> 5)) ? sm[lane] : 0.0f;
#pragma unroll
        for (int o = 16; o > 0; o >>= 1) v += __shfl_xor_sync(0xffffffffu, v, o);
        if (lane == 0) sm[0] = v;
    }
    __syncthreads();
    return sm[0];
}

// ---------------------------------------------------------------------------
// LayerNorm in-place over last dim N (256 threads per row)
// ---------------------------------------------------------------------------
template <int N>
__global__ void ln_kernel(float* __restrict__ x,
                          const float* __restrict__ gamma,
                          const float* __restrict__ beta) {
    constexpr int PER = N / 256;
    size_t row = blockIdx.x;
    float* p = x + row * (size_t)N;
    int tid = threadIdx.x;

    float vals[PER];
    float s = 0.0f;
#pragma unroll
    for (int i = 0; i < PER; i++) { vals[i] = p[tid + i * 256]; s += vals[i]; }
    float m = block_reduce_sum(s) * (1.0f / N);

    float vs = 0.0f;
#pragma unroll
    for (int i = 0; i < PER; i++) { float d = vals[i] - m; vs += d * d; }
    float var = block_reduce_sum(vs) * (1.0f / N);
    float inv = 1.0f / sqrtf(var + 1e-5f);

#pragma unroll
    for (int i = 0; i < PER; i++) {
        int c = tid + i * 256;
        p[c] = (vals[i] - m) * inv * gamma[c] + beta[c];
    }
}

// ---------------------------------------------------------------------------
// LIF multistep, in-place: h[b,t,c] -> spikes. v' = v + (x - v)/2;
// spike if v' >= 1; hard reset to 0.
// ---------------------------------------------------------------------------
__global__ void lif_kernel(float* __restrict__ h, int C) {
    int idx = blockIdx.x * blockDim.x + threadIdx.x;
    if (idx >= Bsz * C) return;
    int b = idx / C, j = idx % C;
    float v = 0.0f;
    size_t base = (size_t)b * Tsz * C + j;
#pragma unroll 4
    for (int t = 0; t < Tsz; t++) {
        size_t o = base + (size_t)t * C;
        float xi = h[o];
        v = v + (xi - v) * 0.5f;
        float s = 0.0f;
        if (v >= 1.0f) { s = 1.0f; v = 0.0f; }
        h[o] = s;
    }
}

// LIF + residual accumulate: x[b,t,c] += spike (only touches x on spikes)
__global__ void lif_add_kernel(const float* __restrict__ h, float* __restrict__ x, int C) {
    int idx = blockIdx.x * blockDim.x + threadIdx.x;
    if (idx >= Bsz * C) return;
    int b = idx / C, j = idx % C;
    float v = 0.0f;
    size_t base = (size_t)b * Tsz * C + j;
#pragma unroll 4
    for (int t = 0; t < Tsz; t++) {
        size_t o = base + (size_t)t * C;
        float xi = h[o];
        v = v + (xi - v) * 0.5f;
        if (v >= 1.0f) { v = 0.0f; x[o] += 1.0f; }
    }
}

// Extract last timestep: out[b,e] = x[b, T-1, e]
__global__ void last_kernel(const float* __restrict__ x, float* __restrict__ out) {
    int i = blockIdx.x * blockDim.x + threadIdx.x;
    if (i < Bsz * Esz) {
        int b = i / Esz, e = i % Esz;
        out[i] = x[((size_t)b * Tsz + (Tsz - 1)) * Esz + e];
    }
}

// ---------------------------------------------------------------------------
extern "C" void kernel_launch(void* const* d_in, const int* in_sizes, int n_in,
                              void* d_out, int out_size) {
    const float* hist  = (const float*)d_in[0];
    const float* pW1   = (const float*)d_in[1];
    const float* pb1   = (const float*)d_in[2];
    const float* pW2   = (const float*)d_in[3];
    const float* pb2   = (const float*)d_in[4];
    const float* fc1_w = (const float*)d_in[5];
    const float* fc1_b = (const float*)d_in[6];
    const float* ln1_g = (const float*)d_in[7];
    const float* ln1_b = (const float*)d_in[8];
    const float* fc2_w = (const float*)d_in[9];
    const float* fc2_b = (const float*)d_in[10];
    const float* ln2_g = (const float*)d_in[11];
    const float* ln2_b = (const float*)d_in[12];

    float *x, *h1, *h2;
    cudaGetSymbolAddress((void**)&x,  g_x);
    cudaGetSymbolAddress((void**)&h1, g_h1);
    cudaGetSymbolAddress((void**)&h2, g_h2);

    proj_kernel<<<ROWS, 128>>>(hist, pW1, pb1, pW2, pb2, x);

    for (int d = 0; d < Dsz; d++) {
        // h1 = x @ fc1_w[d] + fc1_b[d]
        sgemm_bias<<<dim3(Hsz / BN, ROWS / BM), 256>>>(
            x, fc1_w + (size_t)d * Esz * Hsz, fc1_b + d * Hsz, h1, ROWS, Hsz, Esz);
        ln_kernel<Hsz><<<ROWS, 256>>>(h1, ln1_g + d * Hsz, ln1_b + d * Hsz);
        lif_kernel<<<(Bsz * Hsz + 255) / 256, 256>>>(h1, Hsz);

        // h2 = spikes @ fc2_w[d] + fc2_b[d]
        sgemm_bias<<<dim3(Esz / BN, ROWS / BM), 256>>>(
            h1, fc2_w + (size_t)d * Hsz * Esz, fc2_b + d * Esz, h2, ROWS, Esz, Hsz);
        ln_kernel<Esz><<<ROWS, 256>>>(h2, ln2_g + d * Esz, ln2_b + d * Esz);
        lif_add_kernel<<<(Bsz * Esz + 255) / 256, 256>>>(h2, x, Esz);
    }

    last_kernel<<<(Bsz * Esz + 255) / 256, 256>>>(x, (float*)d_out);
}

// round 3
// speedup vs baseline: 2.5045x; 2.5045x over previous
#include <cuda_runtime.h>
#include <cuda_fp16.h>
#include <math.h>
#include <stdint.h>

// Problem dims
#define Bsz  256
#define Tsz  256
#define INsz 4
#define HPsz 64
#define Esz  512
#define Hsz  1024
#define Dsz  4
#define ROWS (Bsz * Tsz)   // 65536

// ---------------------------------------------------------------------------
// Scratch (device globals; no allocation allowed)
// ---------------------------------------------------------------------------
__device__ float  g_x  [(size_t)ROWS * Esz];   // residual stream fp32
__device__ __half g_xhi[(size_t)ROWS * Esz];   // fp16 split of x (hi)
__device__ __half g_xlo[(size_t)ROWS * Esz];   // fp16 split of x (lo)
__device__ float  g_h1 [(size_t)ROWS * Hsz];   // hidden fp32
__device__ __half g_spk[(size_t)ROWS * Hsz];   // spikes fp16 (exact 0/1)
__device__ float  g_h2 [(size_t)ROWS * Esz];   // layer out fp32
// transposed fp16 weight splits: Wt1 [D][H][E], Wt2 [D][E][H]
__device__ __half g_w1hi[(size_t)Dsz * Hsz * Esz];
__device__ __half g_w1lo[(size_t)Dsz * Hsz * Esz];
__device__ __half g_w2hi[(size_t)Dsz * Esz * Hsz];
__device__ __half g_w2lo[(size_t)Dsz * Esz * Hsz];

// ---------------------------------------------------------------------------
// Helpers
// ---------------------------------------------------------------------------
__device__ __forceinline__ uint32_t sw128(uint32_t b) { return b ^ ((b >> 3) & 0x70); }

__device__ __forceinline__ uint32_t s2u(const void* p) {
    uint32_t a;
    asm("{ .reg .u64 t; cvta.to.shared.u64 t, %1; cvt.u32.u64 %0, t; }" : "=r"(a) : "l"(p));
    return a;
}

__device__ __forceinline__ void cp16(uint32_t saddr, const void* g) {
    asm volatile("cp.async.cg.shared.global [%0], [%1], 16;" :: "r"(saddr), "l"(g));
}

#define LDSM4(r0, r1, r2, r3, addr)                                           \
    asm volatile("ldmatrix.sync.aligned.m8n8.x4.shared.b16 {%0,%1,%2,%3}, [%4];" \
                 : "=r"(r0), "=r"(r1), "=r"(r2), "=r"(r3) : "r"(addr))

#define MMA16816(d, a, b)                                                     \
    asm volatile(                                                             \
        "mma.sync.aligned.m16n8k16.row.col.f32.f16.f16.f32 "                  \
        "{%0,%1,%2,%3},{%4,%5,%6,%7},{%8,%9},{%0,%1,%2,%3};"                  \
        : "+f"((d)[0]), "+f"((d)[1]), "+f"((d)[2]), "+f"((d)[3])              \
        : "r"((a)[0]), "r"((a)[1]), "r"((a)[2]), "r"((a)[3]),                 \
          "r"((b)[0]), "r"((b)[1]))

// ---------------------------------------------------------------------------
// Split+transpose weights: src [K][N] fp32 -> dst [N][K] fp16 hi/lo
// ---------------------------------------------------------------------------
__global__ void split_w(const float* __restrict__ W, __half* __restrict__ hi,
                        __half* __restrict__ lo, int K, int N) {
    int idx = blockIdx.x * blockDim.x + threadIdx.x;
    if (idx >= K * N) return;
    int k = idx / N, n = idx % N;
    float w = W[idx];
    __half h = __float2half_rn(w);
    hi[(size_t)n * K + k] = h;
    lo[(size_t)n * K + k] = __float2half_rn(w - __half2float(h));
}

// ---------------------------------------------------------------------------
// GEMM: C[M, Ntot] = Ahi@Bhi^T + Ahi@Blo^T (+ Alo@Bhi^T) + bias
// mma.sync m16n8k16, CTA tile 128x128, BK=64, 8 warps (4x2), double-buffered
// A: [M][K] fp16 row-major;  B: [Ntot][K] fp16 (transposed weights)
// ---------------------------------------------------------------------------
#define OFF_AHI 0
#define OFF_ALO 16384
#define OFF_BHI 32768
#define OFF_BLO 49152
#define STG_SZ  65536
#define SMEM_TOT (2 * STG_SZ)   // 131072 bytes

template <int TERMS>
__device__ __forceinline__ void load_stage(uint32_t sbase,
                                           const __half* A, const __half* Al,
                                           const __half* B, const __half* Bl,
                                           int K, int k0, int tid) {
#pragma unroll
    for (int it = 0; it < 4; it++) {
        int idx = tid + it * 256;
        int r = idx >> 3, c = idx & 7;
        uint32_t so = sw128((uint32_t)(r * 128 + c * 16));
        size_t go = (size_t)r * K + k0 + c * 8;
        cp16(sbase + OFF_AHI + so, A + go);
        if (TERMS == 3) cp16(sbase + OFF_ALO + so, Al + go);
        cp16(sbase + OFF_BHI + so, B + go);
        cp16(sbase + OFF_BLO + so, Bl + go);
    }
    asm volatile("cp.async.commit_group;" ::: "memory");
}

template <int TERMS>
__global__ void __launch_bounds__(256, 1)
gemm_hs(const __half* __restrict__ Ahi, const __half* __restrict__ Alo,
        const __half* __restrict__ Bhi, const __half* __restrict__ Blo,
        const float* __restrict__ bias, float* __restrict__ C,
        int Ntot, int K) {
    extern __shared__ char smc[];
    uint32_t sb = s2u(smc);
    int tid = threadIdx.x;
    int wid = tid >> 5, lane = tid & 31;
    int warp_m = wid >> 1, warp_n = wid & 1;
    int bx = blockIdx.x, by = blockIdx.y;

    const __half* Ah = Ahi + (size_t)(by * 128) * K;
    const __half* Al = Alo + (size_t)(by * 128) * K;
    const __half* Bh = Bhi + (size_t)(bx * 128) * K;
    const __half* Bl = Blo + (size_t)(bx * 128) * K;

    const int NC = K / 64;
    float acc[2][8][4] = {};

    int row_in = lane & 7, grp = lane >> 3;

    load_stage<TERMS>(sb, Ah, Al, Bh, Bl, K, 0, tid);

    for (int c = 0; c < NC; c++) {
        int s = c & 1;
        if (c + 1 < NC) {
            load_stage<TERMS>(sb + (s ^ 1) * STG_SZ, Ah, Al, Bh, Bl, K, (c + 1) * 64, tid);
            asm volatile("cp.async.wait_group 1;" ::: "memory");
        } else {
            asm volatile("cp.async.wait_group 0;" ::: "memory");
        }
        __syncthreads();

        uint32_t stg = sb + s * STG_SZ;
#pragma unroll
        for (int ks = 0; ks < 4; ks++) {
            uint32_t ahi[2][4], alo[2][4];
#pragma unroll
            for (int mf = 0; mf < 2; mf++) {
                int r = warp_m * 32 + mf * 16 + (grp & 1) * 8 + row_in;
                int kb = ks * 32 + (grp >> 1) * 16;
                uint32_t off = sw128((uint32_t)(r * 128 + kb));
                LDSM4(ahi[mf][0], ahi[mf][1], ahi[mf][2], ahi[mf][3], stg + OFF_AHI + off);
                if (TERMS == 3)
                    LDSM4(alo[mf][0], alo[mf][1], alo[mf][2], alo[mf][3], stg + OFF_ALO + off);
            }
            uint32_t bhi[8][2], blo[8][2];
#pragma unroll
            for (int p = 0; p < 4; p++) {
                int r = warp_n * 64 + p * 16 + (grp >> 1) * 8 + row_in;
                int kb = ks * 32 + (grp & 1) * 16;
                uint32_t off = sw128((uint32_t)(r * 128 + kb));
                uint32_t t0, t1, t2, t3;
                LDSM4(t0, t1, t2, t3, stg + OFF_BHI + off);
                bhi[2 * p][0] = t0; bhi[2 * p][1] = t1;
                bhi[2 * p + 1][0] = t2; bhi[2 * p + 1][1] = t3;
                LDSM4(t0, t1, t2, t3, stg + OFF_BLO + off);
                blo[2 * p][0] = t0; blo[2 * p][1] = t1;
                blo[2 * p + 1][0] = t2; blo[2 * p + 1][1] = t3;
            }
#pragma unroll
            for (int mf = 0; mf < 2; mf++) {
#pragma unroll
                for (int nf = 0; nf < 8; nf++) {
                    MMA16816(acc[mf][nf], ahi[mf], bhi[nf]);
                    MMA16816(acc[mf][nf], ahi[mf], blo[nf]);
                    if (TERMS == 3) MMA16816(acc[mf][nf], alo[mf], bhi[nf]);
                }
            }
        }
        __syncthreads();
    }

    // Epilogue: fused bias, direct fp32 stores (float2)
    int col_base = bx * 128 + warp_n * 64 + (lane & 3) * 2;
    int row_base = by * 128 + warp_m * 32 + (lane >> 2);
#pragma unroll
    for (int mf = 0; mf < 2; mf++) {
#pragma unroll
        for (int nf = 0; nf < 8; nf++) {
            int col = col_base + nf * 8;
            float b0 = __ldg(bias + col), b1 = __ldg(bias + col + 1);
            int r0 = row_base + mf * 16;
            float2 v0 = { acc[mf][nf][0] + b0, acc[mf][nf][1] + b1 };
            float2 v1 = { acc[mf][nf][2] + b0, acc[mf][nf][3] + b1 };
            *(float2*)(C + (size_t)r0 * Ntot + col) = v0;
            *(float2*)(C + (size_t)(r0 + 8) * Ntot + col) = v1;
        }
    }
}

// ---------------------------------------------------------------------------
// Input projector: x = gelu(hist @ W1 + b1) @ W2 + b2, plus fp16 hi/lo of x
// ---------------------------------------------------------------------------
__global__ void proj_kernel(const float* __restrict__ hist,
                            const float* __restrict__ W1, const float* __restrict__ b1,
                            const float* __restrict__ W2, const float* __restrict__ b2,
                            float* __restrict__ out,
                            __half* __restrict__ ohi, __half* __restrict__ olo) {
    __shared__ float inr[INsz];
    __shared__ float hp[HPsz];
    int row = blockIdx.x;
    int tid = threadIdx.x;

    if (tid < INsz) inr[tid] = hist[(size_t)row * INsz + tid];
    __syncthreads();

    if (tid < HPsz) {
        float a = b1[tid];
#pragma unroll
        for (int i = 0; i < INsz; i++) a += inr[i] * W1[i * HPsz + tid];
        hp[tid] = 0.5f * a * (1.0f + erff(a * 0.70710678118654752440f));
    }
    __syncthreads();

    for (int o = tid; o < Esz; o += 128) {
        float a = b2[o];
#pragma unroll 8
        for (int j = 0; j < HPsz; j++) a += hp[j] * W2[j * Esz + o];
        size_t off = (size_t)row * Esz + o;
        out[off] = a;
        __half h = __float2half_rn(a);
        ohi[off] = h;
        olo[off] = __float2half_rn(a - __half2float(h));
    }
}

// ---------------------------------------------------------------------------
// Block reduce + LayerNorm (in place, fp32)
// ---------------------------------------------------------------------------
__device__ __forceinline__ float block_reduce_sum(float v) {
    __shared__ float smr[32];
    int lane = threadIdx.x & 31, wid = threadIdx.x >> 5;
#pragma unroll
    for (int o = 16; o > 0; o >>= 1) v += __shfl_xor_sync(0xffffffffu, v, o);
    __syncthreads();
    if (lane == 0) smr[wid] = v;
    __syncthreads();
    if (wid == 0) {
        v = (lane < (int)(blockDim.x >> 5)) ? smr[lane] : 0.0f;
#pragma unroll
        for (int o = 16; o > 0; o >>= 1) v += __shfl_xor_sync(0xffffffffu, v, o);
        if (lane == 0) smr[0] = v;
    }
    __syncthreads();
    return smr[0];
}

template <int N>
__global__ void ln_kernel(float* __restrict__ x,
                          const float* __restrict__ gamma,
                          const float* __restrict__ beta) {
    constexpr int PER = N / 256;
    size_t row = blockIdx.x;
    float* p = x + row * (size_t)N;
    int tid = threadIdx.x;

    float vals[PER];
    float s = 0.0f;
#pragma unroll
    for (int i = 0; i < PER; i++) { vals[i] = p[tid + i * 256]; s += vals[i]; }
    float m = block_reduce_sum(s) * (1.0f / N);

    float vs = 0.0f;
#pragma unroll
    for (int i = 0; i < PER; i++) { float d = vals[i] - m; vs += d * d; }
    float var = block_reduce_sum(vs) * (1.0f / N);
    float inv = 1.0f / sqrtf(var + 1e-5f);

#pragma unroll
    for (int i = 0; i < PER; i++) {
        int c = tid + i * 256;
        p[c] = (vals[i] - m) * inv * gamma[c] + beta[c];
    }
}

// ---------------------------------------------------------------------------
// LIF: read LN'd h (fp32), emit spikes as exact fp16 {0,1}
// ---------------------------------------------------------------------------
__global__ void lif_kernel(const float* __restrict__ h, __half* __restrict__ spk, int C) {
    int idx = blockIdx.x * blockDim.x + threadIdx.x;
    if (idx >= Bsz * C) return;
    int b = idx / C, j = idx % C;
    float v = 0.0f;
    size_t base = (size_t)b * Tsz * C + j;
#pragma unroll 4
    for (int t = 0; t < Tsz; t++) {
        size_t o = base + (size_t)t * C;
        float xi = h[o];
        v = v + (xi - v) * 0.5f;
        float sp = 0.0f;
        if (v >= 1.0f) { sp = 1.0f; v = 0.0f; }
        spk[o] = __float2half_rn(sp);
    }
}

// LIF + residual accumulate + fp16 split refresh of x
__global__ void lif_add_kernel(const float* __restrict__ h, float* __restrict__ x,
                               __half* __restrict__ xhi, __half* __restrict__ xlo, int C) {
    int idx = blockIdx.x * blockDim.x + threadIdx.x;
    if (idx >= Bsz * C) return;
    int b = idx / C, j = idx % C;
    float v = 0.0f;
    size_t base = (size_t)b * Tsz * C + j;
#pragma unroll 4
    for (int t = 0; t < Tsz; t++) {
        size_t o = base + (size_t)t * C;
        float xi = h[o];
        v = v + (xi - v) * 0.5f;
        float xv = x[o];
        if (v >= 1.0f) { v = 0.0f; xv += 1.0f; x[o] = xv; }
        __half hh = __float2half_rn(xv);
        xhi[o] = hh;
        xlo[o] = __float2half_rn(xv - __half2float(hh));
    }
}

// Extract last timestep
__global__ void last_kernel(const float* __restrict__ x, float* __restrict__ out) {
    int i = blockIdx.x * blockDim.x + threadIdx.x;
    if (i < Bsz * Esz) {
        int b = i / Esz, e = i % Esz;
        out[i] = x[((size_t)b * Tsz + (Tsz - 1)) * Esz + e];
    }
}

// ---------------------------------------------------------------------------
extern "C" void kernel_launch(void* const* d_in, const int* in_sizes, int n_in,
                              void* d_out, int out_size) {
    const float* hist  = (const float*)d_in[0];
    const float* pW1   = (const float*)d_in[1];
    const float* pb1   = (const float*)d_in[2];
    const float* pW2   = (const float*)d_in[3];
    const float* pb2   = (const float*)d_in[4];
    const float* fc1_w = (const float*)d_in[5];
    const float* fc1_b = (const float*)d_in[6];
    const float* ln1_g = (const float*)d_in[7];
    const float* ln1_b = (const float*)d_in[8];
    const float* fc2_w = (const float*)d_in[9];
    const float* fc2_b = (const float*)d_in[10];
    const float* ln2_g = (const float*)d_in[11];
    const float* ln2_b = (const float*)d_in[12];

    float *x, *h1, *h2;
    __half *xhi, *xlo, *spk, *w1hi, *w1lo, *w2hi, *w2lo;
    cudaGetSymbolAddress((void**)&x,    g_x);
    cudaGetSymbolAddress((void**)&h1,   g_h1);
    cudaGetSymbolAddress((void**)&h2,   g_h2);
    cudaGetSymbolAddress((void**)&xhi,  g_xhi);
    cudaGetSymbolAddress((void**)&xlo,  g_xlo);
    cudaGetSymbolAddress((void**)&spk,  g_spk);
    cudaGetSymbolAddress((void**)&w1hi, g_w1hi);
    cudaGetSymbolAddress((void**)&w1lo, g_w1lo);
    cudaGetSymbolAddress((void**)&w2hi, g_w2hi);
    cudaGetSymbolAddress((void**)&w2lo, g_w2lo);

    cudaFuncSetAttribute(gemm_hs<3>, cudaFuncAttributeMaxDynamicSharedMemorySize, SMEM_TOT);
    cudaFuncSetAttribute(gemm_hs<2>, cudaFuncAttributeMaxDynamicSharedMemorySize, SMEM_TOT);

    // Split + transpose weights (16 MB of work; trivial)
    for (int d = 0; d < Dsz; d++) {
        size_t o1 = (size_t)d * Esz * Hsz;
        size_t o2 = (size_t)d * Hsz * Esz;
        split_w<<<(Esz * Hsz + 255) / 256, 256>>>(fc1_w + o1, w1hi + o1, w1lo + o1, Esz, Hsz);
        split_w<<<(Hsz * Esz + 255) / 256, 256>>>(fc2_w + o2, w2hi + o2, w2lo + o2, Hsz, Esz);
    }

    proj_kernel<<<ROWS, 128>>>(hist, pW1, pb1, pW2, pb2, x, xhi, xlo);

    for (int d = 0; d < Dsz; d++) {
        size_t o1 = (size_t)d * Hsz * Esz;   // Wt1 [H][E] per layer
        size_t o2 = (size_t)d * Esz * Hsz;   // Wt2 [E][H] per layer

        gemm_hs<3><<<dim3(Hsz / 128, ROWS / 128), 256, SMEM_TOT>>>(
            xhi, xlo, w1hi + o1, w1lo + o1, fc1_b + d * Hsz, h1, Hsz, Esz);
        ln_kernel<Hsz><<<ROWS, 256>>>(h1, ln1_g + d * Hsz, ln1_b + d * Hsz);
        lif_kernel<<<(Bsz * Hsz + 255) / 256, 256>>>(h1, spk, Hsz);

        gemm_hs<2><<<dim3(Esz / 128, ROWS / 128), 256, SMEM_TOT>>>(
            spk, spk, w2hi + o2, w2lo + o2, fc2_b + d * Esz, h2, Esz, Hsz);
        ln_kernel<Esz><<<ROWS, 256>>>(h2, ln2_g + d * Esz, ln2_b + d * Esz);
        lif_add_kernel<<<(Bsz * Esz + 255) / 256, 256>>>(h2, x, xhi, xlo, Esz);
    }

    last_kernel<<<(Bsz * Esz + 255) / 256, 256>>>(x, (float*)d_out);
}

// round 4
// speedup vs baseline: 2.5732x; 1.0275x over previous
#include <cuda_runtime.h>
#include <cuda_fp16.h>
#include <math.h>
#include <stdint.h>

// Problem dims
#define Bsz  256
#define Tsz  256
#define INsz 4
#define HPsz 64
#define Esz  512
#define Hsz  1024
#define Dsz  4
#define ROWS (Bsz * Tsz)   // 65536

// ---------------------------------------------------------------------------
// Scratch (device globals; no allocation allowed)
// ---------------------------------------------------------------------------
__device__ float  g_x  [(size_t)ROWS * Esz];   // residual stream fp32
__device__ __half g_xhi[(size_t)ROWS * Esz];   // fp16 split of x (hi)
__device__ __half g_xlo[(size_t)ROWS * Esz];   // fp16 split of x (lo)
__device__ float  g_h1 [(size_t)ROWS * Hsz];   // hidden fp32
__device__ __half g_spk[(size_t)ROWS * Hsz];   // spikes fp16 (exact 0/1)
__device__ float  g_h2 [(size_t)ROWS * Esz];   // layer out fp32
// transposed fp16 weight splits: Wt1 [D][H][E], Wt2 [D][E][H]
__device__ __half g_w1hi[(size_t)Dsz * Hsz * Esz];
__device__ __half g_w1lo[(size_t)Dsz * Hsz * Esz];
__device__ __half g_w2hi[(size_t)Dsz * Esz * Hsz];
__device__ __half g_w2lo[(size_t)Dsz * Esz * Hsz];

// ---------------------------------------------------------------------------
// Helpers
// ---------------------------------------------------------------------------
__device__ __forceinline__ uint32_t sw128(uint32_t b) { return b ^ ((b >> 3) & 0x70); }

__device__ __forceinline__ uint32_t s2u(const void* p) {
    uint32_t a;
    asm("{ .reg .u64 t; cvta.to.shared.u64 t, %1; cvt.u32.u64 %0, t; }" : "=r"(a) : "l"(p));
    return a;
}

__device__ __forceinline__ void cp16(uint32_t saddr, const void* g) {
    asm volatile("cp.async.cg.shared.global [%0], [%1], 16;" :: "r"(saddr), "l"(g));
}

#define LDSM4(r0, r1, r2, r3, addr)                                           \
    asm volatile("ldmatrix.sync.aligned.m8n8.x4.shared.b16 {%0,%1,%2,%3}, [%4];" \
                 : "=r"(r0), "=r"(r1), "=r"(r2), "=r"(r3) : "r"(addr))

#define MMA16816(d, a, b)                                                     \
    asm volatile(                                                             \
        "mma.sync.aligned.m16n8k16.row.col.f32.f16.f16.f32 "                  \
        "{%0,%1,%2,%3},{%4,%5,%6,%7},{%8,%9},{%0,%1,%2,%3};"                  \
        : "+f"((d)[0]), "+f"((d)[1]), "+f"((d)[2]), "+f"((d)[3])              \
        : "r"((a)[0]), "r"((a)[1]), "r"((a)[2]), "r"((a)[3]),                 \
          "r"((b)[0]), "r"((b)[1]))

// ---------------------------------------------------------------------------
// Split+transpose weights: src [L][K][N] fp32 -> dst [L][N][K] fp16 hi/lo
// grid.y = layer
// ---------------------------------------------------------------------------
__global__ void split_w(const float* __restrict__ W, __half* __restrict__ hi,
                        __half* __restrict__ lo, int K, int N) {
    int idx = blockIdx.x * blockDim.x + threadIdx.x;
    if (idx >= K * N) return;
    size_t lofs = (size_t)blockIdx.y * K * N;
    int k = idx / N, n = idx % N;
    float w = W[lofs + idx];
    __half h = __float2half_rn(w);
    hi[lofs + (size_t)n * K + k] = h;
    lo[lofs + (size_t)n * K + k] = __float2half_rn(w - __half2float(h));
}

// ---------------------------------------------------------------------------
// GEMM: C[M, Ntot] = Ahi@Bhi^T + Ahi@Blo^T (+ Alo@Bhi^T) + bias
// mma.sync m16n8k16, CTA 128x128, BK=64, 8 warps (4x2), double-buffered smem,
// double-buffered fragments (ks-level software pipeline), 1 sync per chunk
// ---------------------------------------------------------------------------
#define OFF_AHI 0
#define OFF_ALO 16384
#define OFF_BHI 32768
#define OFF_BLO 49152
#define STG_SZ  65536
#define SMEM_TOT (2 * STG_SZ)   // 131072 bytes

template <int TERMS>
__device__ __forceinline__ void load_stage(uint32_t sbase,
                                           const __half* A, const __half* Al,
                                           const __half* B, const __half* Bl,
                                           int K, int k0, int tid) {
#pragma unroll
    for (int it = 0; it < 4; it++) {
        int idx = tid + it * 256;
        int r = idx >> 3, c = idx & 7;
        uint32_t so = sw128((uint32_t)(r * 128 + c * 16));
        size_t go = (size_t)r * K + k0 + c * 8;
        cp16(sbase + OFF_AHI + so, A + go);
        if (TERMS == 3) cp16(sbase + OFF_ALO + so, Al + go);
        cp16(sbase + OFF_BHI + so, B + go);
        cp16(sbase + OFF_BLO + so, Bl + go);
    }
    asm volatile("cp.async.commit_group;" ::: "memory");
}

// Load one ks-slice of fragments for this warp
template <int TERMS>
__device__ __forceinline__ void load_frags(uint32_t stg, int ks,
                                           int warp_m, int warp_n, int lane,
                                           uint32_t (&ahi)[2][4], uint32_t (&alo)[2][4],
                                           uint32_t (&bhi)[8][2], uint32_t (&blo)[8][2]) {
    int row_in = lane & 7, grp = lane >> 3;
#pragma unroll
    for (int mf = 0; mf < 2; mf++) {
        int r = warp_m * 32 + mf * 16 + (grp & 1) * 8 + row_in;
        int kb = ks * 32 + (grp >> 1) * 16;
        uint32_t off = sw128((uint32_t)(r * 128 + kb));
        LDSM4(ahi[mf][0], ahi[mf][1], ahi[mf][2], ahi[mf][3], stg + OFF_AHI + off);
        if (TERMS == 3)
            LDSM4(alo[mf][0], alo[mf][1], alo[mf][2], alo[mf][3], stg + OFF_ALO + off);
    }
#pragma unroll
    for (int p = 0; p < 4; p++) {
        int r = warp_n * 64 + p * 16 + (grp >> 1) * 8 + row_in;
        int kb = ks * 32 + (grp & 1) * 16;
        uint32_t off = sw128((uint32_t)(r * 128 + kb));
        uint32_t t0, t1, t2, t3;
        LDSM4(t0, t1, t2, t3, stg + OFF_BHI + off);
        bhi[2 * p][0] = t0; bhi[2 * p][1] = t1;
        bhi[2 * p + 1][0] = t2; bhi[2 * p + 1][1] = t3;
        LDSM4(t0, t1, t2, t3, stg + OFF_BLO + off);
        blo[2 * p][0] = t0; blo[2 * p][1] = t1;
        blo[2 * p + 1][0] = t2; blo[2 * p + 1][1] = t3;
    }
}

template <int TERMS>
__global__ void __launch_bounds__(256, 1)
gemm_hs(const __half* __restrict__ Ahi, const __half* __restrict__ Alo,
        const __half* __restrict__ Bhi, const __half* __restrict__ Blo,
        const float* __restrict__ bias, float* __restrict__ C,
        int Ntot, int K) {
    extern __shared__ char smc[];
    uint32_t sb = s2u(smc);
    int tid = threadIdx.x;
    int wid = tid >> 5, lane = tid & 31;
    int warp_m = wid >> 1, warp_n = wid & 1;
    int bx = blockIdx.x, by = blockIdx.y;

    const __half* Ah = Ahi + (size_t)(by * 128) * K;
    const __half* Al = Alo + (size_t)(by * 128) * K;
    const __half* Bh = Bhi + (size_t)(bx * 128) * K;
    const __half* Bl = Blo + (size_t)(bx * 128) * K;

    const int NC = K / 64;
    float acc[2][8][4] = {};

    // double-buffered fragments
    uint32_t ahi[2][2][4], alo[2][2][4], bhi[2][8][2], blo[2][8][2];

    load_stage<TERMS>(sb, Ah, Al, Bh, Bl, K, 0, tid);

    for (int c = 0; c < NC; c++) {
        uint32_t stg = sb + (c & 1) * STG_SZ;
        asm volatile("cp.async.wait_group 0;" ::: "memory");
        __syncthreads();
        if (c + 1 < NC)
            load_stage<TERMS>(sb + ((c + 1) & 1) * STG_SZ, Ah, Al, Bh, Bl, K, (c + 1) * 64, tid);

        load_frags<TERMS>(stg, 0, warp_m, warp_n, lane, ahi[0], alo[0], bhi[0], blo[0]);
#pragma unroll
        for (int ks = 0; ks < 4; ks++) {
            int cur = ks & 1, nxt = cur ^ 1;
            if (ks < 3)
                load_frags<TERMS>(stg, ks + 1, warp_m, warp_n, lane,
                                  ahi[nxt], alo[nxt], bhi[nxt], blo[nxt]);
#pragma unroll
            for (int mf = 0; mf < 2; mf++) {
#pragma unroll
                for (int nf = 0; nf < 8; nf++) {
                    MMA16816(acc[mf][nf], ahi[cur][mf], bhi[cur][nf]);
                    MMA16816(acc[mf][nf], ahi[cur][mf], blo[cur][nf]);
                    if (TERMS == 3) MMA16816(acc[mf][nf], alo[cur][mf], bhi[cur][nf]);
                }
            }
        }
    }

    // Epilogue: fused bias, direct fp32 stores (float2)
    int col_base = bx * 128 + warp_n * 64 + (lane & 3) * 2;
    int row_base = by * 128 + warp_m * 32 + (lane >> 2);
    float bsr[8][2];
#pragma unroll
    for (int nf = 0; nf < 8; nf++) {
        bsr[nf][0] = __ldg(bias + col_base + nf * 8);
        bsr[nf][1] = __ldg(bias + col_base + nf * 8 + 1);
    }
#pragma unroll
    for (int mf = 0; mf < 2; mf++) {
#pragma unroll
        for (int nf = 0; nf < 8; nf++) {
            int col = col_base + nf * 8;
            int r0 = row_base + mf * 16;
            float2 v0 = { acc[mf][nf][0] + bsr[nf][0], acc[mf][nf][1] + bsr[nf][1] };
            float2 v1 = { acc[mf][nf][2] + bsr[nf][0], acc[mf][nf][3] + bsr[nf][1] };
            *(float2*)(C + (size_t)r0 * Ntot + col) = v0;
            *(float2*)(C + (size_t)(r0 + 8) * Ntot + col) = v1;
        }
    }
}

// ---------------------------------------------------------------------------
// Input projector: x = gelu(hist @ W1 + b1) @ W2 + b2, plus fp16 hi/lo of x
// ---------------------------------------------------------------------------
__global__ void proj_kernel(const float* __restrict__ hist,
                            const float* __restrict__ W1, const float* __restrict__ b1,
                            const float* __restrict__ W2, const float* __restrict__ b2,
                            float* __restrict__ out,
                            __half* __restrict__ ohi, __half* __restrict__ olo) {
    __shared__ float inr[INsz];
    __shared__ float hp[HPsz];
    int row = blockIdx.x;
    int tid = threadIdx.x;

    if (tid < INsz) inr[tid] = hist[(size_t)row * INsz + tid];
    __syncthreads();

    if (tid < HPsz) {
        float a = b1[tid];
#pragma unroll
        for (int i = 0; i < INsz; i++) a += inr[i] * W1[i * HPsz + tid];
        hp[tid] = 0.5f * a * (1.0f + erff(a * 0.70710678118654752440f));
    }
    __syncthreads();

    for (int o = tid; o < Esz; o += 128) {
        float a = b2[o];
#pragma unroll 8
        for (int j = 0; j < HPsz; j++) a += hp[j] * W2[j * Esz + o];
        size_t off = (size_t)row * Esz + o;
        out[off] = a;
        __half h = __float2half_rn(a);
        ohi[off] = h;
        olo[off] = __float2half_rn(a - __half2float(h));
    }
}

// ---------------------------------------------------------------------------
// Block reduce + LayerNorm (in place, fp32, float4 vectorized)
// ---------------------------------------------------------------------------
__device__ __forceinline__ float block_reduce_sum(float v) {
    __shared__ float smr[32];
    int lane = threadIdx.x & 31, wid = threadIdx.x >> 5;
#pragma unroll
    for (int o = 16; o > 0; o >>= 1) v += __shfl_xor_sync(0xffffffffu, v, o);
    __syncthreads();
    if (lane == 0) smr[wid] = v;
    __syncthreads();
    if (wid == 0) {
        v = (lane < (int)(blockDim.x >> 5)) ? smr[lane] : 0.0f;
#pragma unroll
        for (int o = 16; o > 0; o >>= 1) v += __shfl_xor_sync(0xffffffffu, v, o);
        if (lane == 0) smr[0] = v;
    }
    __syncthreads();
    return smr[0];
}

template <int N, int NTHR>
__global__ void ln_kernel(float* __restrict__ x,
                          const float* __restrict__ gamma,
                          const float* __restrict__ beta) {
    constexpr int PER = N / (NTHR * 4);
    size_t row = blockIdx.x;
    float4* p = (float4*)(x + row * (size_t)N);
    const float4* g4 = (const float4*)gamma;
    const float4* b4 = (const float4*)beta;
    int tid = threadIdx.x;

    float4 vals[PER];
    float s = 0.0f;
#pragma unroll
    for (int i = 0; i < PER; i++) {
        vals[i] = p[tid + i * NTHR];
        s += vals[i].x + vals[i].y + vals[i].z + vals[i].w;
    }
    float m = block_reduce_sum(s) * (1.0f / N);

    float vs = 0.0f;
#pragma unroll
    for (int i = 0; i < PER; i++) {
        float dx = vals[i].x - m, dy = vals[i].y - m;
        float dz = vals[i].z - m, dw = vals[i].w - m;
        vs += dx * dx + dy * dy + dz * dz + dw * dw;
    }
    float var = block_reduce_sum(vs) * (1.0f / N);
    float inv = 1.0f / sqrtf(var + 1e-5f);

#pragma unroll
    for (int i = 0; i < PER; i++) {
        int c = tid + i * NTHR;
        float4 gg = g4[c], bb = b4[c];
        float4 o;
        o.x = (vals[i].x - m) * inv * gg.x + bb.x;
        o.y = (vals[i].y - m) * inv * gg.y + bb.y;
        o.z = (vals[i].z - m) * inv * gg.z + bb.z;
        o.w = (vals[i].w - m) * inv * gg.w + bb.w;
        p[c] = o;
    }
}

// ---------------------------------------------------------------------------
// LIF: read LN'd h (fp32), emit spikes as exact fp16 {0,1}
// ---------------------------------------------------------------------------
__global__ void lif_kernel(const float* __restrict__ h, __half* __restrict__ spk, int C) {
    int idx = blockIdx.x * blockDim.x + threadIdx.x;
    if (idx >= Bsz * C) return;
    int b = idx / C, j = idx % C;
    float v = 0.0f;
    size_t base = (size_t)b * Tsz * C + j;
#pragma unroll 4
    for (int t = 0; t < Tsz; t++) {
        size_t o = base + (size_t)t * C;
        float xi = h[o];
        v = v + (xi - v) * 0.5f;
        float sp = 0.0f;
        if (v >= 1.0f) { sp = 1.0f; v = 0.0f; }
        spk[o] = __float2half_rn(sp);
    }
}

// LIF + residual accumulate + fp16 split refresh of x
__global__ void lif_add_kernel(const float* __restrict__ h, float* __restrict__ x,
                               __half* __restrict__ xhi, __half* __restrict__ xlo, int C) {
    int idx = blockIdx.x * blockDim.x + threadIdx.x;
    if (idx >= Bsz * C) return;
    int b = idx / C, j = idx % C;
    float v = 0.0f;
    size_t base = (size_t)b * Tsz * C + j;
#pragma unroll 4
    for (int t = 0; t < Tsz; t++) {
        size_t o = base + (size_t)t * C;
        float xi = h[o];
        v = v + (xi - v) * 0.5f;
        float xv = x[o];
        if (v >= 1.0f) { v = 0.0f; xv += 1.0f; x[o] = xv; }
        __half hh = __float2half_rn(xv);
        xhi[o] = hh;
        xlo[o] = __float2half_rn(xv - __half2float(hh));
    }
}

// Extract last timestep
__global__ void last_kernel(const float* __restrict__ x, float* __restrict__ out) {
    int i = blockIdx.x * blockDim.x + threadIdx.x;
    if (i < Bsz * Esz) {
        int b = i / Esz, e = i % Esz;
        out[i] = x[((size_t)b * Tsz + (Tsz - 1)) * Esz + e];
    }
}

// ---------------------------------------------------------------------------
extern "C" void kernel_launch(void* const* d_in, const int* in_sizes, int n_in,
                              void* d_out, int out_size) {
    const float* hist  = (const float*)d_in[0];
    const float* pW1   = (const float*)d_in[1];
    const float* pb1   = (const float*)d_in[2];
    const float* pW2   = (const float*)d_in[3];
    const float* pb2   = (const float*)d_in[4];
    const float* fc1_w = (const float*)d_in[5];
    const float* fc1_b = (const float*)d_in[6];
    const float* ln1_g = (const float*)d_in[7];
    const float* ln1_b = (const float*)d_in[8];
    const float* fc2_w = (const float*)d_in[9];
    const float* fc2_b = (const float*)d_in[10];
    const float* ln2_g = (const float*)d_in[11];
    const float* ln2_b = (const float*)d_in[12];

    float *x, *h1, *h2;
    __half *xhi, *xlo, *spk, *w1hi, *w1lo, *w2hi, *w2lo;
    cudaGetSymbolAddress((void**)&x,    g_x);
    cudaGetSymbolAddress((void**)&h1,   g_h1);
    cudaGetSymbolAddress((void**)&h2,   g_h2);
    cudaGetSymbolAddress((void**)&xhi,  g_xhi);
    cudaGetSymbolAddress((void**)&xlo,  g_xlo);
    cudaGetSymbolAddress((void**)&spk,  g_spk);
    cudaGetSymbolAddress((void**)&w1hi, g_w1hi);
    cudaGetSymbolAddress((void**)&w1lo, g_w1lo);
    cudaGetSymbolAddress((void**)&w2hi, g_w2hi);
    cudaGetSymbolAddress((void**)&w2lo, g_w2lo);

    cudaFuncSetAttribute(gemm_hs<3>, cudaFuncAttributeMaxDynamicSharedMemorySize, SMEM_TOT);
    cudaFuncSetAttribute(gemm_hs<2>, cudaFuncAttributeMaxDynamicSharedMemorySize, SMEM_TOT);

    // Split + transpose weights, all layers in 2 launches
    split_w<<<dim3((Esz * Hsz + 255) / 256, Dsz), 256>>>(fc1_w, w1hi, w1lo, Esz, Hsz);
    split_w<<<dim3((Hsz * Esz + 255) / 256, Dsz), 256>>>(fc2_w, w2hi, w2lo, Hsz, Esz);

    proj_kernel<<<ROWS, 128>>>(hist, pW1, pb1, pW2, pb2, x, xhi, xlo);

    for (int d = 0; d < Dsz; d++) {
        size_t o1 = (size_t)d * Hsz * Esz;   // Wt1 [H][E] per layer
        size_t o2 = (size_t)d * Esz * Hsz;   // Wt2 [E][H] per layer

        gemm_hs<3><<<dim3(Hsz / 128, ROWS / 128), 256, SMEM_TOT>>>(
            xhi, xlo, w1hi + o1, w1lo + o1, fc1_b + d * Hsz, h1, Hsz, Esz);
        ln_kernel<Hsz, 256><<<ROWS, 256>>>(h1, ln1_g + d * Hsz, ln1_b + d * Hsz);
        lif_kernel<<<(Bsz * Hsz + 255) / 256, 256>>>(h1, spk, Hsz);

        gemm_hs<2><<<dim3(Esz / 128, ROWS / 128), 256, SMEM_TOT>>>(
            spk, spk, w2hi + o2, w2lo + o2, fc2_b + d * Esz, h2, Esz, Hsz);
        ln_kernel<Esz, 128><<<ROWS, 128>>>(h2, ln2_g + d * Esz, ln2_b + d * Esz);
        lif_add_kernel<<<(Bsz * Esz + 255) / 256, 256>>>(h2, x, xhi, xlo, Esz);
    }

    last_kernel<<<(Bsz * Esz + 255) / 256, 256>>>(x, (float*)d_out);
}